// round 1
// baseline (speedup 1.0000x reference)
#include <cuda_runtime.h>
#include <cuda_bf16.h>
#include <cstdint>

// Problem shapes (fixed by setup_inputs)
#define NX 16384   // rows of x
#define NS 4096    // rows of support
#define DD 256     // feature dim

// Scratch: bf16 copies + row squared-norms (device globals; no allocation)
__device__ __align__(16) __nv_bfloat16 g_xbf[NX * DD];
__device__ __align__(16) __nv_bfloat16 g_sbf[NS * DD];
__device__ float g_xsq[NX];
__device__ float g_ssq[NS];

// ---------------------------------------------------------------------------
// Prep: convert fp32 -> bf16 and compute per-row squared norms (fp32 exact).
// One block (256 threads) per row.
// ---------------------------------------------------------------------------
__global__ void prep_kernel(const float* __restrict__ x,
                            const float* __restrict__ s) {
    int row = blockIdx.x;
    const float* src;
    __nv_bfloat16* dst;
    float* sqout;
    if (row < NX) {
        src = x + (size_t)row * DD;
        dst = g_xbf + (size_t)row * DD;
        sqout = g_xsq + row;
    } else {
        int r = row - NX;
        src = s + (size_t)r * DD;
        dst = g_sbf + (size_t)r * DD;
        sqout = g_ssq + r;
    }
    int t = threadIdx.x;
    float v = src[t];
    dst[t] = __float2bfloat16(v);
    float p = v * v;
#pragma unroll
    for (int o = 16; o; o >>= 1) p += __shfl_xor_sync(0xffffffffu, p, o);
    __shared__ float wsum[8];
    if ((t & 31) == 0) wsum[t >> 5] = p;
    __syncthreads();
    if (t == 0) {
        float acc = 0.f;
#pragma unroll
        for (int i = 0; i < 8; i++) acc += wsum[i];
        *sqout = acc;
    }
}

// ---------------------------------------------------------------------------
// Main fused GEMM + RBF epilogue.
// Block tile 128(M) x 128(N), BK=32, 8 warps: 4 along M x 2 along N,
// warp tile 32x64 via mma.sync.m16n8k16 bf16 (2 M-tiles x 8 N-tiles).
// SMEM row stride = 40 bf16 (80B) -> conflict-free fragment loads.
// ---------------------------------------------------------------------------
#define BK 32
#define LDS_STRIDE 40

__device__ __forceinline__ void mma16816(float* c, const uint32_t* a,
                                         const uint32_t* b) {
    asm volatile(
        "mma.sync.aligned.m16n8k16.row.col.f32.bf16.bf16.f32 "
        "{%0,%1,%2,%3}, {%4,%5,%6,%7}, {%8,%9}, {%0,%1,%2,%3};\n"
        : "+f"(c[0]), "+f"(c[1]), "+f"(c[2]), "+f"(c[3])
        : "r"(a[0]), "r"(a[1]), "r"(a[2]), "r"(a[3]), "r"(b[0]), "r"(b[1]));
}

__global__ void __launch_bounds__(256, 2)
rbf_gemm_kernel(float* __restrict__ out) {
    __shared__ __nv_bfloat16 As[128 * LDS_STRIDE];
    __shared__ __nv_bfloat16 Bs[128 * LDS_STRIDE];

    const int tid = threadIdx.x;
    const int wid = tid >> 5;
    const int lane = tid & 31;
    const int warpM = wid & 3;   // 0..3 -> 32-row slab
    const int warpN = wid >> 2;  // 0..1 -> 64-col slab
    const int g = lane >> 2;     // group id 0..7
    const int t4 = lane & 3;     // 0..3

    const int mBlock = blockIdx.y * 128;
    const int nBlock = blockIdx.x * 128;

    float acc[2][8][4];
#pragma unroll
    for (int i = 0; i < 2; i++)
#pragma unroll
        for (int j = 0; j < 8; j++)
#pragma unroll
            for (int k = 0; k < 4; k++) acc[i][j][k] = 0.f;

    for (int kk = 0; kk < DD; kk += BK) {
        // Global -> SMEM: 128 rows x 32 bf16 per tile, 4B..8B vector moves.
        // Each thread moves 4 uint2 (16 bf16) per tile.
#pragma unroll
        for (int i = 0; i < 4; i++) {
            int c = tid + i * 256;
            int row = c >> 3;       // 8 uint2 chunks per row (32 elems)
            int kc = c & 7;
            uint2 va = *reinterpret_cast<const uint2*>(
                g_xbf + (size_t)(mBlock + row) * DD + kk + kc * 4);
            *reinterpret_cast<uint2*>(As + row * LDS_STRIDE + kc * 4) = va;
            uint2 vb = *reinterpret_cast<const uint2*>(
                g_sbf + (size_t)(nBlock + row) * DD + kk + kc * 4);
            *reinterpret_cast<uint2*>(Bs + row * LDS_STRIDE + kc * 4) = vb;
        }
        __syncthreads();

#pragma unroll
        for (int ks = 0; ks < BK; ks += 16) {
            uint32_t a[2][4];
            uint32_t b[8][2];
#pragma unroll
            for (int mt = 0; mt < 2; mt++) {
                int r = warpM * 32 + mt * 16 + g;
                const __nv_bfloat16* p = As + r * LDS_STRIDE + ks + t4 * 2;
                a[mt][0] = *reinterpret_cast<const uint32_t*>(p);
                a[mt][1] = *reinterpret_cast<const uint32_t*>(p + 8 * LDS_STRIDE);
                a[mt][2] = *reinterpret_cast<const uint32_t*>(p + 8);
                a[mt][3] = *reinterpret_cast<const uint32_t*>(p + 8 * LDS_STRIDE + 8);
            }
#pragma unroll
            for (int nt = 0; nt < 8; nt++) {
                int n = warpN * 64 + nt * 8 + g;
                const __nv_bfloat16* p = Bs + n * LDS_STRIDE + ks + t4 * 2;
                b[nt][0] = *reinterpret_cast<const uint32_t*>(p);
                b[nt][1] = *reinterpret_cast<const uint32_t*>(p + 8);
            }
#pragma unroll
            for (int mt = 0; mt < 2; mt++)
#pragma unroll
                for (int nt = 0; nt < 8; nt++)
                    mma16816(acc[mt][nt], a[mt], b[nt]);
        }
        __syncthreads();
    }

    // Epilogue: sq = xsq + ssq - 2*dot, clamp >= 0, out = exp(-sq).
    // MUFU.EX2 throughput (rt_SMSP=8 per warp-instr) is ~16us chip-wide: fine.
#pragma unroll
    for (int mt = 0; mt < 2; mt++) {
        int r0 = mBlock + warpM * 32 + mt * 16 + g;
        float xs0 = g_xsq[r0];
        float xs1 = g_xsq[r0 + 8];
#pragma unroll
        for (int nt = 0; nt < 8; nt++) {
            int ccol = nBlock + warpN * 64 + nt * 8 + t4 * 2;
            float ss0 = g_ssq[ccol];
            float ss1 = g_ssq[ccol + 1];
            const float* a4 = acc[mt][nt];

            float sq00 = fmaxf(fmaf(-2.f, a4[0], xs0 + ss0), 0.f);
            float sq01 = fmaxf(fmaf(-2.f, a4[1], xs0 + ss1), 0.f);
            float sq10 = fmaxf(fmaf(-2.f, a4[2], xs1 + ss0), 0.f);
            float sq11 = fmaxf(fmaf(-2.f, a4[3], xs1 + ss1), 0.f);

            float2 o0 = make_float2(__expf(-sq00), __expf(-sq01));
            float2 o1 = make_float2(__expf(-sq10), __expf(-sq11));

            *reinterpret_cast<float2*>(out + (size_t)r0 * NS + ccol) = o0;
            *reinterpret_cast<float2*>(out + (size_t)(r0 + 8) * NS + ccol) = o1;
        }
    }
}

// ---------------------------------------------------------------------------
extern "C" void kernel_launch(void* const* d_in, const int* in_sizes, int n_in,
                              void* d_out, int out_size) {
    // x is the larger input; be robust to argument order.
    const float* x = (const float*)d_in[0];
    const float* s = (const float*)d_in[1];
    if (n_in >= 2 && in_sizes[0] < in_sizes[1]) {
        x = (const float*)d_in[1];
        s = (const float*)d_in[0];
    }
    float* out = (float*)d_out;

    prep_kernel<<<NX + NS, 256>>>(x, s);

    dim3 grid(NS / 128, NX / 128);  // 32 x 128 = 4096 blocks
    rbf_gemm_kernel<<<grid, 256>>>(out);
}

// round 3
// speedup vs baseline: 1.4716x; 1.4716x over previous
#include <cuda_runtime.h>
#include <cuda_bf16.h>
#include <cstdint>

#define NX 16384
#define NS 4096
#define DD 256

// Scratch (device globals; no allocation allowed)
__device__ __align__(16) __nv_bfloat16 g_xbf[NX * DD];
__device__ __align__(16) __nv_bfloat16 g_sbf[NS * DD];
__device__ float g_xsq[NX];
__device__ float g_ssq[NS];

// ---------------------------------------------------------------------------
// Prep: fp32 -> bf16 + row squared norms. One warp per row, 8 floats/lane.
// ---------------------------------------------------------------------------
__global__ void prep_kernel(const float* __restrict__ x,
                            const float* __restrict__ s) {
    int warp = (blockIdx.x * blockDim.x + threadIdx.x) >> 5;
    int lane = threadIdx.x & 31;
    if (warp >= NX + NS) return;
    const float* src;
    __nv_bfloat16* dst;
    float* sqout;
    if (warp < NX) {
        src = x + (size_t)warp * DD; dst = g_xbf + (size_t)warp * DD; sqout = g_xsq + warp;
    } else {
        int r = warp - NX;
        src = s + (size_t)r * DD; dst = g_sbf + (size_t)r * DD; sqout = g_ssq + r;
    }
    float4 v0 = reinterpret_cast<const float4*>(src)[lane * 2];
    float4 v1 = reinterpret_cast<const float4*>(src)[lane * 2 + 1];
    __nv_bfloat162 p0 = __floats2bfloat162_rn(v0.x, v0.y);
    __nv_bfloat162 p1 = __floats2bfloat162_rn(v0.z, v0.w);
    __nv_bfloat162 p2 = __floats2bfloat162_rn(v1.x, v1.y);
    __nv_bfloat162 p3 = __floats2bfloat162_rn(v1.z, v1.w);
    uint4 pk;
    pk.x = *reinterpret_cast<uint32_t*>(&p0);
    pk.y = *reinterpret_cast<uint32_t*>(&p1);
    pk.z = *reinterpret_cast<uint32_t*>(&p2);
    pk.w = *reinterpret_cast<uint32_t*>(&p3);
    reinterpret_cast<uint4*>(dst)[lane] = pk;
    float p = v0.x * v0.x + v0.y * v0.y + v0.z * v0.z + v0.w * v0.w +
              v1.x * v1.x + v1.y * v1.y + v1.z * v1.z + v1.w * v1.w;
#pragma unroll
    for (int o = 16; o; o >>= 1) p += __shfl_xor_sync(0xffffffffu, p, o);
    if (lane == 0) *sqout = p;
}

// ---------------------------------------------------------------------------
// Pipelined HMMA GEMM + RBF epilogue.
// CTA 128x128, BK=32, 4-stage cp.async, 8 warps (4M x 2N), warp tile 32x64.
// SMEM rows padded to 40 bf16 (80B): conflict-free ldmatrix + cp.async stores.
// ---------------------------------------------------------------------------
#define BK 32
#define STAGE_BYTES 20480  // A 128*80 + B 128*80
#define NSTAGE 4
#define DYN_SMEM (NSTAGE * STAGE_BYTES)  // 81920

__device__ __forceinline__ uint32_t cvta_s(const void* p) {
    uint32_t a;
    asm("{ .reg .u64 t; cvta.to.shared.u64 t, %1; cvt.u32.u64 %0, t; }"
        : "=r"(a) : "l"(p));
    return a;
}
__device__ __forceinline__ void cp16(uint32_t d, const void* s) {
    asm volatile("cp.async.cg.shared.global [%0], [%1], 16;\n" :: "r"(d), "l"(s));
}
__device__ __forceinline__ void ldsm_x4(uint32_t* r, uint32_t a) {
    asm volatile("ldmatrix.sync.aligned.m8n8.x4.shared.b16 {%0,%1,%2,%3}, [%4];"
                 : "=r"(r[0]), "=r"(r[1]), "=r"(r[2]), "=r"(r[3]) : "r"(a));
}
__device__ __forceinline__ void mma16816(float* c, const uint32_t* a,
                                         const uint32_t* b) {
    asm volatile(
        "mma.sync.aligned.m16n8k16.row.col.f32.bf16.bf16.f32 "
        "{%0,%1,%2,%3}, {%4,%5,%6,%7}, {%8,%9}, {%0,%1,%2,%3};\n"
        : "+f"(c[0]), "+f"(c[1]), "+f"(c[2]), "+f"(c[3])
        : "r"(a[0]), "r"(a[1]), "r"(a[2]), "r"(a[3]), "r"(b[0]), "r"(b[1]));
}

// Load one BK=32 stage: A 128x32 bf16 (8KB) + B 128x32 (8KB) = 1024 granules.
__device__ __forceinline__ void load_stage(uint32_t sbase, const char* aS,
                                           const char* bS, int kk, int tid) {
    int row = tid >> 2, j = tid & 3;
    uint32_t soff = row * 80 + j * 16;
    size_t goff = (size_t)row * 512 + (size_t)kk * 2 + j * 16;
#pragma unroll
    for (int half = 0; half < 2; half++) {
        cp16(sbase + half * 64 * 80 + soff, aS + half * (size_t)64 * 512 + goff);
        cp16(sbase + 10240 + half * 64 * 80 + soff,
             bS + half * (size_t)64 * 512 + goff);
    }
    asm volatile("cp.async.commit_group;\n");
}

__global__ void __launch_bounds__(256, 2)
rbf_hmma_kernel(float* __restrict__ out) {
    extern __shared__ __align__(128) char dsm[];
    __shared__ float ssq_s[128];

    const int tid = threadIdx.x;
    const int wid = tid >> 5;
    const int lane = tid & 31;
    const int warpM = wid & 3;   // 4 warps along M (32 rows each)
    const int warpN = wid >> 2;  // 2 warps along N (64 cols each)
    const int mBlock = blockIdx.y * 128;
    const int nBlock = blockIdx.x * 128;

    const uint32_t sm0 = cvta_s(dsm);
    const char* aS = (const char*)g_xbf + (size_t)mBlock * 512;
    const char* bS = (const char*)g_sbf + (size_t)nBlock * 512;

    if (tid < 128) ssq_s[tid] = g_ssq[nBlock + tid];

    // Prologue: fill 3 of 4 stages (K iters: 256/32 = 8)
    load_stage(sm0 + 0 * STAGE_BYTES, aS, bS, 0, tid);
    load_stage(sm0 + 1 * STAGE_BYTES, aS, bS, 32, tid);
    load_stage(sm0 + 2 * STAGE_BYTES, aS, bS, 64, tid);

    float acc[2][8][4];
#pragma unroll
    for (int i = 0; i < 2; i++)
#pragma unroll
        for (int j = 0; j < 8; j++)
#pragma unroll
            for (int k = 0; k < 4; k++) acc[i][j][k] = 0.f;

    // Per-lane ldmatrix base offsets (within a stage)
    const uint32_t aFragOff = (warpM * 32 + (lane & 15)) * 80 + (lane >> 4) * 16;
    const uint32_t bFragOff =
        10240 + (warpN * 64 + (lane & 15)) * 80 + (lane >> 4) * 16;

#pragma unroll
    for (int it = 0; it < 8; it++) {
        if (it < 6)
            asm volatile("cp.async.wait_group 2;\n");
        else if (it == 6)
            asm volatile("cp.async.wait_group 1;\n");
        else
            asm volatile("cp.async.wait_group 0;\n");
        __syncthreads();

        if (it + 3 < 8)
            load_stage(sm0 + ((it + 3) & 3) * STAGE_BYTES, aS, bS, (it + 3) * 32,
                       tid);

        const uint32_t sb = sm0 + (it & 3) * STAGE_BYTES;
#pragma unroll
        for (int ks = 0; ks < 2; ks++) {
            uint32_t a[2][4], b[4][4];
#pragma unroll
            for (int mt = 0; mt < 2; mt++)
                ldsm_x4(a[mt], sb + aFragOff + mt * 16 * 80 + ks * 32);
#pragma unroll
            for (int bt = 0; bt < 4; bt++)
                ldsm_x4(b[bt], sb + bFragOff + bt * 16 * 80 + ks * 32);
#pragma unroll
            for (int mt = 0; mt < 2; mt++)
#pragma unroll
                for (int bt = 0; bt < 4; bt++) {
                    uint32_t b0[2] = {b[bt][0], b[bt][2]};
                    uint32_t b1[2] = {b[bt][1], b[bt][3]};
                    mma16816(acc[mt][bt * 2 + 0], a[mt], b0);
                    mma16816(acc[mt][bt * 2 + 1], a[mt], b1);
                }
        }
    }

    // Epilogue: sq = xsq + ssq - 2*dot, clamp, exp.
    const int g = lane >> 2;
    const int t4 = lane & 3;
#pragma unroll
    for (int mt = 0; mt < 2; mt++) {
        int r0 = mBlock + warpM * 32 + mt * 16 + g;
        float xs0 = g_xsq[r0];
        float xs1 = g_xsq[r0 + 8];
        float* o0 = out + (size_t)r0 * NS + nBlock + warpN * 64;
        float* o1 = o0 + (size_t)8 * NS;
#pragma unroll
        for (int nt = 0; nt < 8; nt++) {
            int c = nt * 8 + t4 * 2;
            float ss0 = ssq_s[warpN * 64 + c];
            float ss1 = ssq_s[warpN * 64 + c + 1];
            const float* a4 = acc[mt][nt];
            float2 v0, v1;
            v0.x = __expf(-fmaxf(fmaf(-2.f, a4[0], xs0 + ss0), 0.f));
            v0.y = __expf(-fmaxf(fmaf(-2.f, a4[1], xs0 + ss1), 0.f));
            v1.x = __expf(-fmaxf(fmaf(-2.f, a4[2], xs1 + ss0), 0.f));
            v1.y = __expf(-fmaxf(fmaf(-2.f, a4[3], xs1 + ss1), 0.f));
            *reinterpret_cast<float2*>(o0 + c) = v0;
            *reinterpret_cast<float2*>(o1 + c) = v1;
        }
    }
}

// ---------------------------------------------------------------------------
extern "C" void kernel_launch(void* const* d_in, const int* in_sizes, int n_in,
                              void* d_out, int out_size) {
    const float* x = (const float*)d_in[0];
    const float* s = (const float*)d_in[1];
    if (n_in >= 2 && in_sizes[0] < in_sizes[1]) {
        x = (const float*)d_in[1];
        s = (const float*)d_in[0];
    }
    float* out = (float*)d_out;

    cudaFuncSetAttribute(rbf_hmma_kernel,
                         cudaFuncAttributeMaxDynamicSharedMemorySize, DYN_SMEM);

    prep_kernel<<<(NX + NS) / 8, 256>>>(x, s);

    dim3 grid(NS / 128, NX / 128);  // 32 x 128 = 4096 CTAs
    rbf_hmma_kernel<<<grid, 256, DYN_SMEM>>>(out);
}